// round 1
// baseline (speedup 1.0000x reference)
#include <cuda_runtime.h>

#define NN 50000
#define NP 50048          // 391 * 128
#define FF 128
#define EE 800000

// ---------------- scratch (device globals; no allocation) ----------------
__device__ float g_ew[3][EE];
__device__ int   g_perm[3][EE];
__device__ int   g_cnt[3][NN];
__device__ int   g_off[3][NN];
__device__ int   g_cur[3][NN];
__device__ float g_dinv[3][NN];
__device__ float g_xw[(size_t)NP * FF];    // xW0, then hW1
__device__ float g_agg[(size_t)NP * FF];   // agg0 -> h (in place) -> agg1
__device__ float g_bnsum[4][FF];           // sum0, sq0, sum1, sq1
__device__ float g_bnp[4][FF];             // mu0, rs0, mu1, rs1

// packed fp32x2 FMA (Blackwell): 2 FMA per instruction on the fma pipe
#define FMA2(acc, a, b) asm("fma.rn.f32x2 %0, %1, %2, %0;" : "+l"(acc) : "l"(a), "l"(b))

// ---------------- small setup kernels ----------------
__global__ void k_zero() {
    int i = blockIdx.x * blockDim.x + threadIdx.x;
    if (i < 3 * NN) (&g_cnt[0][0])[i] = 0;
    if (i < 4 * FF) (&g_bnsum[0][0])[i] = 0.f;
}

__global__ void k_count(const int* __restrict__ e0, const int* __restrict__ e1,
                        const int* __restrict__ e2) {
    int i = blockIdx.x * blockDim.x + threadIdx.x;
    if (i >= 3 * EE) return;
    int s = i / EE, j = i - s * EE;
    const int* col = (s == 0 ? e0 : s == 1 ? e1 : e2) + EE;
    atomicAdd(&g_cnt[s][col[j]], 1);
}

__global__ void k_scan() {
    __shared__ int sh[1024];
    __shared__ int carry;
    int s = blockIdx.x;
    int tid = threadIdx.x;
    if (tid == 0) carry = 0;
    __syncthreads();
    for (int base = 0; base < NN; base += 1024) {
        int i = base + tid;
        int v = (i < NN) ? g_cnt[s][i] : 0;
        sh[tid] = v;
        __syncthreads();
        for (int off = 1; off < 1024; off <<= 1) {
            int t = (tid >= off) ? sh[tid - off] : 0;
            __syncthreads();
            sh[tid] += t;
            __syncthreads();
        }
        int excl = sh[tid] - v;
        if (i < NN) {
            int o = carry + excl;
            g_off[s][i] = o;
            g_cur[s][i] = o;
        }
        int tot = sh[1023];
        __syncthreads();
        if (tid == 0) carry += tot;
        __syncthreads();
    }
}

__global__ void k_fill(const int* __restrict__ e0, const int* __restrict__ e1,
                       const int* __restrict__ e2) {
    int i = blockIdx.x * blockDim.x + threadIdx.x;
    if (i >= 3 * EE) return;
    int s = i / EE, j = i - s * EE;
    const int* col = (s == 0 ? e0 : s == 1 ? e1 : e2) + EE;
    int pos = atomicAdd(&g_cur[s][col[j]], 1);
    g_perm[s][pos] = j;
}

__global__ void k_deg() {
    int i = blockIdx.x * blockDim.x + threadIdx.x;
    if (i >= 3 * NN) return;
    int s = i / NN, n = i - s * NN;
    int o = g_off[s][n], c = g_cnt[s][n];
    float d = 0.f;
    for (int k = 0; k < c; ++k) d += g_ew[s][g_perm[s][o + k]];
    g_dinv[s][n] = (c > 0) ? rsqrtf(d) : 0.f;
}

// ---------------- edge MLP: ew = sigmoid(relu(|x_r - x_c| Wa1^T + ba1) . Wa2 + ba2)
// 128-edge x 128-H tile per block, K=128 in 16 steps of 8; hidden stays in regs.
__global__ void __launch_bounds__(256) k_edge_mlp(
    const float* __restrict__ x, const int* __restrict__ ei, int set,
    const float* __restrict__ Wa1, const float* __restrict__ ba1,
    const float* __restrict__ Wa2, const float* __restrict__ ba2) {
    extern __shared__ float sm[];
    float* Ws = sm;                    // [128][132]  Ws[f][h] = Wa1[h][f]
    float* As = sm + 128 * 132;        // [2][8][132] abs-diff k-tiles
    const int tid = threadIdx.x;
#pragma unroll
    for (int it = 0; it < 16; ++it) {
        int idx = tid + 256 * it;
        int h = idx >> 5, f4 = idx & 31;
        float4 w = *(const float4*)(Wa1 + h * 128 + f4 * 4);
        Ws[(f4 * 4 + 0) * 132 + h] = w.x;
        Ws[(f4 * 4 + 1) * 132 + h] = w.y;
        Ws[(f4 * 4 + 2) * 132 + h] = w.z;
        Ws[(f4 * 4 + 3) * 132 + h] = w.w;
    }
    const int e0 = blockIdx.x * 128;
    const int eL = tid >> 1;
    const int jL = (tid & 1) * 4;
    const float* xr = x + (size_t)ei[e0 + eL] * FF;
    const float* xc = x + (size_t)ei[EE + e0 + eL] * FF;
    const int tx = tid & 15, ty = tid >> 4;
    {   // stage k-tile 0
        float4 a = *(const float4*)(xr + jL);
        float4 b = *(const float4*)(xc + jL);
        As[(jL + 0) * 132 + eL] = fabsf(a.x - b.x);
        As[(jL + 1) * 132 + eL] = fabsf(a.y - b.y);
        As[(jL + 2) * 132 + eL] = fabsf(a.z - b.z);
        As[(jL + 3) * 132 + eL] = fabsf(a.w - b.w);
    }
    __syncthreads();

    unsigned long long acc[8][4];
#pragma unroll
    for (int r = 0; r < 8; ++r)
#pragma unroll
        for (int q = 0; q < 4; ++q) acc[r][q] = 0ull;

    for (int kt = 0; kt < 16; ++kt) {
        int buf = kt & 1;
        if (kt < 15) {
            int k0 = (kt + 1) * 8;
            float4 a = *(const float4*)(xr + k0 + jL);
            float4 b = *(const float4*)(xc + k0 + jL);
            float* D = As + (buf ^ 1) * 8 * 132;
            D[(jL + 0) * 132 + eL] = fabsf(a.x - b.x);
            D[(jL + 1) * 132 + eL] = fabsf(a.y - b.y);
            D[(jL + 2) * 132 + eL] = fabsf(a.z - b.z);
            D[(jL + 3) * 132 + eL] = fabsf(a.w - b.w);
        }
        const float* A = As + buf * 8 * 132;
#pragma unroll
        for (int kk = 0; kk < 8; ++kk) {
            const float* wrow = Ws + (kt * 8 + kk) * 132 + tx * 8;
            ulonglong2 b0 = *(const ulonglong2*)(wrow);
            ulonglong2 b1 = *(const ulonglong2*)(wrow + 4);
            float4 a0 = *(const float4*)(A + kk * 132 + ty * 8);
            float4 a1 = *(const float4*)(A + kk * 132 + ty * 8 + 4);
            float av[8] = {a0.x, a0.y, a0.z, a0.w, a1.x, a1.y, a1.z, a1.w};
#pragma unroll
            for (int r = 0; r < 8; ++r) {
                unsigned long long ad;
                unsigned au = __float_as_uint(av[r]);
                asm("mov.b64 %0, {%1,%1};" : "=l"(ad) : "r"(au));
                FMA2(acc[r][0], ad, b0.x);
                FMA2(acc[r][1], ad, b0.y);
                FMA2(acc[r][2], ad, b1.x);
                FMA2(acc[r][3], ad, b1.y);
            }
        }
        __syncthreads();
    }
    // epilogue: relu + dot(Wa2) reduction + sigmoid
    float bb[8], w2[8];
#pragma unroll
    for (int c = 0; c < 8; ++c) {
        int h = tx * 8 + c;
        bb[c] = ba1[h];
        w2[c] = Wa2[h];
    }
    float b2 = ba2[0];
#pragma unroll
    for (int r = 0; r < 8; ++r) {
        float p = 0.f;
#pragma unroll
        for (int q = 0; q < 4; ++q) {
            unsigned long long a = acc[r][q];
            float lo = __uint_as_float((unsigned)a);
            float hi = __uint_as_float((unsigned)(a >> 32));
            p += fmaxf(lo + bb[2 * q], 0.f) * w2[2 * q];
            p += fmaxf(hi + bb[2 * q + 1], 0.f) * w2[2 * q + 1];
        }
        p += __shfl_xor_sync(0xffffffffu, p, 1);
        p += __shfl_xor_sync(0xffffffffu, p, 2);
        p += __shfl_xor_sync(0xffffffffu, p, 4);
        p += __shfl_xor_sync(0xffffffffu, p, 8);
        if (tx == 0) {
            float z = p + b2;
            g_ew[set][e0 + ty * 8 + r] = 1.f / (1.f + expf(-z));
        }
    }
}

// ---------------- node GEMM: C[n][h] = sum_f A[n][f] * W[h][f], C = g_xw
__global__ void __launch_bounds__(256) k_gemm(
    const float* __restrict__ Aext, int nrows, const float* __restrict__ W, int useExt) {
    extern __shared__ float sm[];
    float* Ws = sm;
    float* As = sm + 128 * 132;
    const float* A = useExt ? Aext : (const float*)g_agg;
    const int tid = threadIdx.x;
#pragma unroll
    for (int it = 0; it < 16; ++it) {
        int idx = tid + 256 * it;
        int h = idx >> 5, f4 = idx & 31;
        float4 w = *(const float4*)(W + h * 128 + f4 * 4);
        Ws[(f4 * 4 + 0) * 132 + h] = w.x;
        Ws[(f4 * 4 + 1) * 132 + h] = w.y;
        Ws[(f4 * 4 + 2) * 132 + h] = w.z;
        Ws[(f4 * 4 + 3) * 132 + h] = w.w;
    }
    const int n0 = blockIdx.x * 128;
    const int eL = tid >> 1;
    const int jL = (tid & 1) * 4;
    const int nr = n0 + eL;
    const bool ok = nr < nrows;
    const float* ap = A + (size_t)nr * FF;
    const int tx = tid & 15, ty = tid >> 4;
    {
        float4 a = ok ? *(const float4*)(ap + jL) : make_float4(0, 0, 0, 0);
        As[(jL + 0) * 132 + eL] = a.x;
        As[(jL + 1) * 132 + eL] = a.y;
        As[(jL + 2) * 132 + eL] = a.z;
        As[(jL + 3) * 132 + eL] = a.w;
    }
    __syncthreads();

    unsigned long long acc[8][4];
#pragma unroll
    for (int r = 0; r < 8; ++r)
#pragma unroll
        for (int q = 0; q < 4; ++q) acc[r][q] = 0ull;

    for (int kt = 0; kt < 16; ++kt) {
        int buf = kt & 1;
        if (kt < 15) {
            int k0 = (kt + 1) * 8;
            float4 a = ok ? *(const float4*)(ap + k0 + jL) : make_float4(0, 0, 0, 0);
            float* D = As + (buf ^ 1) * 8 * 132;
            D[(jL + 0) * 132 + eL] = a.x;
            D[(jL + 1) * 132 + eL] = a.y;
            D[(jL + 2) * 132 + eL] = a.z;
            D[(jL + 3) * 132 + eL] = a.w;
        }
        const float* Ab = As + buf * 8 * 132;
#pragma unroll
        for (int kk = 0; kk < 8; ++kk) {
            const float* wrow = Ws + (kt * 8 + kk) * 132 + tx * 8;
            ulonglong2 b0 = *(const ulonglong2*)(wrow);
            ulonglong2 b1 = *(const ulonglong2*)(wrow + 4);
            float4 a0 = *(const float4*)(Ab + kk * 132 + ty * 8);
            float4 a1 = *(const float4*)(Ab + kk * 132 + ty * 8 + 4);
            float av[8] = {a0.x, a0.y, a0.z, a0.w, a1.x, a1.y, a1.z, a1.w};
#pragma unroll
            for (int r = 0; r < 8; ++r) {
                unsigned long long ad;
                unsigned au = __float_as_uint(av[r]);
                asm("mov.b64 %0, {%1,%1};" : "=l"(ad) : "r"(au));
                FMA2(acc[r][0], ad, b0.x);
                FMA2(acc[r][1], ad, b0.y);
                FMA2(acc[r][2], ad, b1.x);
                FMA2(acc[r][3], ad, b1.y);
            }
        }
        __syncthreads();
    }
#pragma unroll
    for (int r = 0; r < 8; ++r) {
        int n = n0 + ty * 8 + r;   // grid covers exactly NP rows
        float4 o0, o1;
        o0.x = __uint_as_float((unsigned)acc[r][0]);
        o0.y = __uint_as_float((unsigned)(acc[r][0] >> 32));
        o0.z = __uint_as_float((unsigned)acc[r][1]);
        o0.w = __uint_as_float((unsigned)(acc[r][1] >> 32));
        o1.x = __uint_as_float((unsigned)acc[r][2]);
        o1.y = __uint_as_float((unsigned)(acc[r][2] >> 32));
        o1.z = __uint_as_float((unsigned)acc[r][3]);
        o1.w = __uint_as_float((unsigned)(acc[r][3] >> 32));
        *(float4*)(g_xw + (size_t)n * FF + tx * 8) = o0;
        *(float4*)(g_xw + (size_t)n * FF + tx * 8 + 4) = o1;
    }
}

// ---------------- aggregation: warp-per-node CSR gather over all 3 sets
__global__ void k_agg(const int* __restrict__ e0, const int* __restrict__ e1,
                      const int* __restrict__ e2) {
    int w = (blockIdx.x * blockDim.x + threadIdx.x) >> 5;
    if (w >= NN) return;
    int lane = threadIdx.x & 31;
    const float* src = (const float*)g_xw;
    float4 acc = make_float4(0, 0, 0, 0);
#pragma unroll
    for (int s = 0; s < 3; ++s) {
        int c = g_cnt[s][w];
        if (c == 0) continue;
        int o = g_off[s][w];
        float dc = g_dinv[s][w];
        const int* rows = (s == 0) ? e0 : (s == 1) ? e1 : e2;
        float4 pa = make_float4(0, 0, 0, 0);
        for (int k = 0; k < c; ++k) {
            int e = g_perm[s][o + k];
            int r = rows[e];
            float wt = g_ew[s][e] * g_dinv[s][r];
            float4 v = *(const float4*)(src + (size_t)r * FF + lane * 4);
            pa.x = fmaf(wt, v.x, pa.x);
            pa.y = fmaf(wt, v.y, pa.y);
            pa.z = fmaf(wt, v.z, pa.z);
            pa.w = fmaf(wt, v.w, pa.w);
        }
        acc.x = fmaf(dc, pa.x, acc.x);
        acc.y = fmaf(dc, pa.y, acc.y);
        acc.z = fmaf(dc, pa.z, acc.z);
        acc.w = fmaf(dc, pa.w, acc.w);
    }
    *(float4*)(g_agg + (size_t)w * FF + lane * 4) = acc;
}

// ---------------- bias + relu + BN stats (in place on g_agg)
__global__ void k_stats(const float* __restrict__ bias, int layer) {
    int c = threadIdx.x;
    float s = 0.f, q = 0.f;
    float b3 = 3.f * bias[c];
    for (int n = blockIdx.x; n < NN; n += gridDim.x) {
        float v = g_agg[(size_t)n * FF + c] + b3;
        v = fmaxf(v, 0.f);
        g_agg[(size_t)n * FF + c] = v;
        s += v;
        q += v * v;
    }
    atomicAdd(&g_bnsum[2 * layer][c], s);
    atomicAdd(&g_bnsum[2 * layer + 1][c], q);
}

__global__ void k_bnfin(int layer) {
    int c = threadIdx.x;
    float mu = g_bnsum[2 * layer][c] / (float)NN;
    float var = g_bnsum[2 * layer + 1][c] / (float)NN - mu * mu;
    g_bnp[2 * layer][c] = mu;
    g_bnp[2 * layer + 1][c] = rsqrtf(var + 1e-5f);
}

__global__ void k_bnapply(const float* __restrict__ gamma, const float* __restrict__ beta) {
    int i = blockIdx.x * blockDim.x + threadIdx.x;
    if (i >= NN * 32) return;
    int cb = (i & 31) * 4;
    float4 v = ((float4*)g_agg)[i];
    v.x = fmaxf((v.x - g_bnp[0][cb + 0]) * g_bnp[1][cb + 0] * gamma[cb + 0] + beta[cb + 0], 0.f);
    v.y = fmaxf((v.y - g_bnp[0][cb + 1]) * g_bnp[1][cb + 1] * gamma[cb + 1] + beta[cb + 1], 0.f);
    v.z = fmaxf((v.z - g_bnp[0][cb + 2]) * g_bnp[1][cb + 2] * gamma[cb + 2] + beta[cb + 2], 0.f);
    v.w = fmaxf((v.w - g_bnp[0][cb + 3]) * g_bnp[1][cb + 3] * gamma[cb + 3] + beta[cb + 3], 0.f);
    ((float4*)g_agg)[i] = v;
}

__global__ void k_final(const float* __restrict__ x, const float* __restrict__ gamma,
                        const float* __restrict__ beta, float* __restrict__ out) {
    int i = blockIdx.x * blockDim.x + threadIdx.x;
    if (i >= NN * 32) return;
    int cb = (i & 31) * 4;
    float4 v = ((const float4*)g_agg)[i];
    float4 xv = ((const float4*)x)[i];
    v.x = (v.x - g_bnp[2][cb + 0]) * g_bnp[3][cb + 0] * gamma[cb + 0] + beta[cb + 0] + xv.x;
    v.y = (v.y - g_bnp[2][cb + 1]) * g_bnp[3][cb + 1] * gamma[cb + 1] + beta[cb + 1] + xv.y;
    v.z = (v.z - g_bnp[2][cb + 2]) * g_bnp[3][cb + 2] * gamma[cb + 2] + beta[cb + 2] + xv.z;
    v.w = (v.w - g_bnp[2][cb + 3]) * g_bnp[3][cb + 3] * gamma[cb + 3] + beta[cb + 3] + xv.w;
    ((float4*)out)[i] = v;
}

// ---------------- launch ----------------
extern "C" void kernel_launch(void* const* d_in, const int* in_sizes, int n_in,
                              void* d_out, int out_size) {
    const float* x   = (const float*)d_in[0];
    const int*   e0  = (const int*)d_in[1];
    const int*   e1  = (const int*)d_in[2];
    const int*   e2  = (const int*)d_in[3];
    const float* Wa1 = (const float*)d_in[4];
    const float* ba1 = (const float*)d_in[5];
    const float* Wa2 = (const float*)d_in[6];
    const float* ba2 = (const float*)d_in[7];
    const float* W0  = (const float*)d_in[8];
    const float* b0  = (const float*)d_in[9];
    const float* W1  = (const float*)d_in[10];
    const float* b1  = (const float*)d_in[11];
    const float* g0  = (const float*)d_in[12];
    const float* be0 = (const float*)d_in[13];
    const float* g1  = (const float*)d_in[14];
    const float* be1 = (const float*)d_in[15];
    float* out = (float*)d_out;

    const int SMEM = (128 * 132 + 2 * 8 * 132) * 4;  // 76032 B
    cudaFuncSetAttribute(k_edge_mlp, cudaFuncAttributeMaxDynamicSharedMemorySize, SMEM);
    cudaFuncSetAttribute(k_gemm, cudaFuncAttributeMaxDynamicSharedMemorySize, SMEM);

    k_zero<<<(3 * NN + 255) / 256, 256>>>();
    k_count<<<(3 * EE + 255) / 256, 256>>>(e0, e1, e2);
    k_scan<<<3, 1024>>>();
    k_fill<<<(3 * EE + 255) / 256, 256>>>(e0, e1, e2);

    const int* es[3] = {e0, e1, e2};
    for (int s = 0; s < 3; ++s)
        k_edge_mlp<<<EE / 128, 256, SMEM>>>(x, es[s], s, Wa1 + s * 128 * 128,
                                            ba1 + s * 128, Wa2 + s * 128, ba2 + s);
    k_deg<<<(3 * NN + 255) / 256, 256>>>();

    // layer 0
    k_gemm<<<NP / 128, 256, SMEM>>>(x, NN, W0, 1);
    k_agg<<<(NN * 32 + 255) / 256, 256>>>(e0, e1, e2);
    k_stats<<<512, 128>>>(b0, 0);
    k_bnfin<<<1, 128>>>(0);
    k_bnapply<<<(NN * 32 + 255) / 256, 256>>>(g0, be0);

    // layer 1
    k_gemm<<<NP / 128, 256, SMEM>>>(nullptr, NP, W1, 0);
    k_agg<<<(NN * 32 + 255) / 256, 256>>>(e0, e1, e2);
    k_stats<<<512, 128>>>(b1, 1);
    k_bnfin<<<1, 128>>>(1);
    k_final<<<(NN * 32 + 255) / 256, 256>>>(x, g1, be1, out);
}

// round 3
// speedup vs baseline: 1.3782x; 1.3782x over previous
#include <cuda_runtime.h>
#include <cstdint>

#define NN 50000
#define NP 50048          // 391 * 128
#define FF 128
#define EE 800000
#define NTILES 3125       // EE / 256
#define TTILES 9375       // 3 * NTILES

// ---------------- scratch (device globals; no allocation) ----------------
__device__ float g_ew[3][EE];
__device__ int   g_perm[3][EE];
__device__ int   g_cnt[3][NN];
__device__ int   g_off[3][NN];
__device__ int   g_cur[3][NN];
__device__ float g_dinv[3][NN];
__device__ float g_xw[(size_t)NP * FF];    // xW0, then hW1
__device__ float g_agg[(size_t)NP * FF];   // agg0 -> h (in place) -> agg1
__device__ float g_bnsum[4][FF];           // sum0, sq0, sum1, sq1
__device__ float g_bnp[4][FF];             // mu0, rs0, mu1, rs1

// packed fp32x2 FMA (Blackwell)
#define FMA2(acc, a, b) asm("fma.rn.f32x2 %0, %1, %2, %0;" : "+l"(acc) : "l"(a), "l"(b))

__device__ __forceinline__ uint32_t f2tf32(float v) {
    uint32_t u;
    asm("cvt.rna.tf32.f32 %0, %1;" : "=r"(u) : "f"(v));
    return u;
}

// warp-level tensor-core MMA, m16n8k8 tf32 (sm_80+, works on plain sm_103 target)
__device__ __forceinline__ void mma8(float* c, const uint32_t* a, uint32_t b0, uint32_t b1) {
    asm volatile(
        "mma.sync.aligned.m16n8k8.row.col.f32.tf32.tf32.f32 "
        "{%0,%1,%2,%3}, {%4,%5,%6,%7}, {%8,%9}, {%0,%1,%2,%3};"
        : "+f"(c[0]), "+f"(c[1]), "+f"(c[2]), "+f"(c[3])
        : "r"(a[0]), "r"(a[1]), "r"(a[2]), "r"(a[3]), "r"(b0), "r"(b1));
}

// ---------------- small setup kernels ----------------
__global__ void k_zero() {
    int i = blockIdx.x * blockDim.x + threadIdx.x;
    if (i < 3 * NN) (&g_cnt[0][0])[i] = 0;
    if (i < 4 * FF) (&g_bnsum[0][0])[i] = 0.f;
}

__global__ void k_count(const int* __restrict__ e0, const int* __restrict__ e1,
                        const int* __restrict__ e2) {
    int i = blockIdx.x * blockDim.x + threadIdx.x;
    if (i >= 3 * EE) return;
    int s = i / EE, j = i - s * EE;
    const int* col = (s == 0 ? e0 : s == 1 ? e1 : e2) + EE;
    atomicAdd(&g_cnt[s][col[j]], 1);
}

__global__ void k_scan() {
    __shared__ int sh[1024];
    __shared__ int carry;
    int s = blockIdx.x;
    int tid = threadIdx.x;
    if (tid == 0) carry = 0;
    __syncthreads();
    for (int base = 0; base < NN; base += 1024) {
        int i = base + tid;
        int v = (i < NN) ? g_cnt[s][i] : 0;
        sh[tid] = v;
        __syncthreads();
        for (int off = 1; off < 1024; off <<= 1) {
            int t = (tid >= off) ? sh[tid - off] : 0;
            __syncthreads();
            sh[tid] += t;
            __syncthreads();
        }
        int excl = sh[tid] - v;
        if (i < NN) {
            int o = carry + excl;
            g_off[s][i] = o;
            g_cur[s][i] = o;
        }
        int tot = sh[1023];
        __syncthreads();
        if (tid == 0) carry += tot;
        __syncthreads();
    }
}

__global__ void k_fill(const int* __restrict__ e0, const int* __restrict__ e1,
                       const int* __restrict__ e2) {
    int i = blockIdx.x * blockDim.x + threadIdx.x;
    if (i >= 3 * EE) return;
    int s = i / EE, j = i - s * EE;
    const int* col = (s == 0 ? e0 : s == 1 ? e1 : e2) + EE;
    int pos = atomicAdd(&g_cur[s][col[j]], 1);
    g_perm[s][pos] = j;
}

__global__ void k_deg() {
    int i = blockIdx.x * blockDim.x + threadIdx.x;
    if (i >= 3 * NN) return;
    int s = i / NN, n = i - s * NN;
    int o = g_off[s][n], c = g_cnt[s][n];
    float d = 0.f;
    for (int k = 0; k < c; ++k) d += g_ew[s][g_perm[s][o + k]];
    g_dinv[s][n] = (c > 0) ? rsqrtf(d) : 0.f;
}

// ---------------- edge MLP via mma.sync tf32 tensor cores ----------------
// persistent: 148 CTAs x 256 threads; tile = 256 edges, N=128 hidden, K=128 features.
// SMEM: A[256][133] (tf32 bits), W[128][132] (tf32 bits), ba1[128], Wa2[128].
#define AS_STRIDE 133
#define WS_STRIDE 132
#define SM_WOFF   (256 * AS_STRIDE)               // floats
#define SM_B1OFF  (SM_WOFF + 128 * WS_STRIDE)
#define SM_W2OFF  (SM_B1OFF + 128)
#define SM_EMLP_BYTES ((SM_W2OFF + 128) * 4)

__global__ void __launch_bounds__(256, 1) k_edge_mlp_mma(
    const float* __restrict__ x,
    const int* __restrict__ e0, const int* __restrict__ e1, const int* __restrict__ e2,
    const float* __restrict__ Wa1, const float* __restrict__ ba1,
    const float* __restrict__ Wa2, const float* __restrict__ ba2) {
    extern __shared__ char smc[];
    uint32_t* As = (uint32_t*)smc;
    uint32_t* Ws = As + SM_WOFF;
    float* Bb = (float*)(As + SM_B1OFF);
    float* W2 = (float*)(As + SM_W2OFF);

    const int tid = threadIdx.x;
    const int w = tid >> 5;
    const int l = tid & 31;
    const int g = l >> 2;
    const int t = l & 3;
    const int rowbase = w * 32;

    int cur_set = -1;
    const int* ei = e0;
    float b2 = 0.f;

    for (int T = blockIdx.x; T < TTILES; T += 148) {
        int set = T / NTILES;
        int tile = T - set * NTILES;
        if (set != cur_set) {
            __syncthreads();   // ensure previous tile's Ws reads complete
            const float* W = Wa1 + set * 128 * 128;
#pragma unroll
            for (int it = 0; it < 16; ++it) {
                int idx = tid + it * 256;
                int h = idx >> 5, f = (idx & 31) * 4;
                float4 v = *(const float4*)(W + h * 128 + f);
                uint32_t* dst = Ws + h * WS_STRIDE + f;
                dst[0] = f2tf32(v.x);
                dst[1] = f2tf32(v.y);
                dst[2] = f2tf32(v.z);
                dst[3] = f2tf32(v.w);
            }
            if (tid < 128) {
                Bb[tid] = ba1[set * 128 + tid];
                W2[tid] = Wa2[set * 128 + tid];
            }
            ei = (set == 0) ? e0 : (set == 1) ? e1 : e2;
            b2 = ba2[set];
            cur_set = set;
            __syncthreads();
        }
        const int eb = tile * 256;

        // ---- stage A = tf32(|x[r] - x[c]|), row-major stride 133 (conflict-free writes)
        {
            int r = ei[eb + tid];
            int c = ei[EE + eb + tid];
            const float4* xr = (const float4*)(x + (size_t)r * FF);
            const float4* xc = (const float4*)(x + (size_t)c * FF);
            uint32_t* arow = As + tid * AS_STRIDE;
#pragma unroll
            for (int j = 0; j < 32; ++j) {
                float4 a = xr[j], b = xc[j];
                arow[4 * j + 0] = f2tf32(fabsf(a.x - b.x));
                arow[4 * j + 1] = f2tf32(fabsf(a.y - b.y));
                arow[4 * j + 2] = f2tf32(fabsf(a.z - b.z));
                arow[4 * j + 3] = f2tf32(fabsf(a.w - b.w));
            }
        }
        __syncthreads();

        // ---- MMA mainloop: warp computes rows [rowbase, rowbase+32) x 128 H
        float acc[2][16][4];
#pragma unroll
        for (int mb = 0; mb < 2; ++mb)
#pragma unroll
            for (int nb = 0; nb < 16; ++nb)
#pragma unroll
                for (int q = 0; q < 4; ++q) acc[mb][nb][q] = 0.f;

        for (int kb = 0; kb < 16; ++kb) {
            const int kc = kb * 8 + t;
            uint32_t af[2][4];
#pragma unroll
            for (int mb = 0; mb < 2; ++mb) {
                int m0 = rowbase + mb * 16 + g;
                af[mb][0] = As[m0 * AS_STRIDE + kc];
                af[mb][1] = As[(m0 + 8) * AS_STRIDE + kc];
                af[mb][2] = As[m0 * AS_STRIDE + kc + 4];
                af[mb][3] = As[(m0 + 8) * AS_STRIDE + kc + 4];
            }
#pragma unroll
            for (int nb = 0; nb < 16; ++nb) {
                uint32_t b0 = Ws[(nb * 8 + g) * WS_STRIDE + kc];
                uint32_t b1 = Ws[(nb * 8 + g) * WS_STRIDE + kc + 4];
                mma8(acc[0][nb], af[0], b0, b1);
                mma8(acc[1][nb], af[1], b0, b1);
            }
        }

        // ---- epilogue: relu(acc + ba1) . Wa2, reduce over H, sigmoid
        float s[4] = {0.f, 0.f, 0.f, 0.f};
#pragma unroll
        for (int nb = 0; nb < 16; ++nb) {
            int h0 = nb * 8 + 2 * t;
            float bb0 = Bb[h0], bb1 = Bb[h0 + 1];
            float w20 = W2[h0], w21 = W2[h0 + 1];
            s[0] += fmaxf(acc[0][nb][0] + bb0, 0.f) * w20 + fmaxf(acc[0][nb][1] + bb1, 0.f) * w21;
            s[1] += fmaxf(acc[0][nb][2] + bb0, 0.f) * w20 + fmaxf(acc[0][nb][3] + bb1, 0.f) * w21;
            s[2] += fmaxf(acc[1][nb][0] + bb0, 0.f) * w20 + fmaxf(acc[1][nb][1] + bb1, 0.f) * w21;
            s[3] += fmaxf(acc[1][nb][2] + bb0, 0.f) * w20 + fmaxf(acc[1][nb][3] + bb1, 0.f) * w21;
        }
#pragma unroll
        for (int i = 0; i < 4; ++i) {
            float v = s[i];
            v += __shfl_xor_sync(0xffffffffu, v, 1);
            v += __shfl_xor_sync(0xffffffffu, v, 2);
            if (t == 0) {
                int rl = rowbase + (i >> 1) * 16 + (i & 1) * 8 + g;
                float z = v + b2;
                g_ew[set][eb + rl] = 1.f / (1.f + expf(-z));
            }
        }
        __syncthreads();   // A reuse safe for next tile
    }
}

// ---------------- node GEMM: C[n][h] = sum_f A[n][f] * W[h][f], C = g_xw
__global__ void __launch_bounds__(256) k_gemm(
    const float* __restrict__ Aext, int nrows, const float* __restrict__ W, int useExt) {
    extern __shared__ float smf[];
    float* Ws = smf;
    float* As = smf + 128 * 132;
    const float* A = useExt ? Aext : (const float*)g_agg;
    const int tid = threadIdx.x;
#pragma unroll
    for (int it = 0; it < 16; ++it) {
        int idx = tid + 256 * it;
        int h = idx >> 5, f4 = idx & 31;
        float4 w = *(const float4*)(W + h * 128 + f4 * 4);
        Ws[(f4 * 4 + 0) * 132 + h] = w.x;
        Ws[(f4 * 4 + 1) * 132 + h] = w.y;
        Ws[(f4 * 4 + 2) * 132 + h] = w.z;
        Ws[(f4 * 4 + 3) * 132 + h] = w.w;
    }
    const int n0 = blockIdx.x * 128;
    const int eL = tid >> 1;
    const int jL = (tid & 1) * 4;
    const int nr = n0 + eL;
    const bool ok = nr < nrows;
    const float* ap = A + (size_t)nr * FF;
    const int tx = tid & 15, ty = tid >> 4;
    {
        float4 a = ok ? *(const float4*)(ap + jL) : make_float4(0, 0, 0, 0);
        As[(jL + 0) * 132 + eL] = a.x;
        As[(jL + 1) * 132 + eL] = a.y;
        As[(jL + 2) * 132 + eL] = a.z;
        As[(jL + 3) * 132 + eL] = a.w;
    }
    __syncthreads();

    unsigned long long acc[8][4];
#pragma unroll
    for (int r = 0; r < 8; ++r)
#pragma unroll
        for (int q = 0; q < 4; ++q) acc[r][q] = 0ull;

    for (int kt = 0; kt < 16; ++kt) {
        int buf = kt & 1;
        if (kt < 15) {
            int k0 = (kt + 1) * 8;
            float4 a = ok ? *(const float4*)(ap + k0 + jL) : make_float4(0, 0, 0, 0);
            float* D = As + (buf ^ 1) * 8 * 132;
            D[(jL + 0) * 132 + eL] = a.x;
            D[(jL + 1) * 132 + eL] = a.y;
            D[(jL + 2) * 132 + eL] = a.z;
            D[(jL + 3) * 132 + eL] = a.w;
        }
        const float* Ab = As + buf * 8 * 132;
#pragma unroll
        for (int kk = 0; kk < 8; ++kk) {
            const float* wrow = Ws + (kt * 8 + kk) * 132 + tx * 8;
            ulonglong2 b0 = *(const ulonglong2*)(wrow);
            ulonglong2 b1 = *(const ulonglong2*)(wrow + 4);
            float4 a0 = *(const float4*)(Ab + kk * 132 + ty * 8);
            float4 a1 = *(const float4*)(Ab + kk * 132 + ty * 8 + 4);
            float av[8] = {a0.x, a0.y, a0.z, a0.w, a1.x, a1.y, a1.z, a1.w};
#pragma unroll
            for (int r = 0; r < 8; ++r) {
                unsigned long long ad;
                unsigned au = __float_as_uint(av[r]);
                asm("mov.b64 %0, {%1,%1};" : "=l"(ad) : "r"(au));
                FMA2(acc[r][0], ad, b0.x);
                FMA2(acc[r][1], ad, b0.y);
                FMA2(acc[r][2], ad, b1.x);
                FMA2(acc[r][3], ad, b1.y);
            }
        }
        __syncthreads();
    }
#pragma unroll
    for (int r = 0; r < 8; ++r) {
        int n = n0 + ty * 8 + r;
        float4 o0, o1;
        o0.x = __uint_as_float((unsigned)acc[r][0]);
        o0.y = __uint_as_float((unsigned)(acc[r][0] >> 32));
        o0.z = __uint_as_float((unsigned)acc[r][1]);
        o0.w = __uint_as_float((unsigned)(acc[r][1] >> 32));
        o1.x = __uint_as_float((unsigned)acc[r][2]);
        o1.y = __uint_as_float((unsigned)(acc[r][2] >> 32));
        o1.z = __uint_as_float((unsigned)acc[r][3]);
        o1.w = __uint_as_float((unsigned)(acc[r][3] >> 32));
        *(float4*)(g_xw + (size_t)n * FF + tx * 8) = o0;
        *(float4*)(g_xw + (size_t)n * FF + tx * 8 + 4) = o1;
    }
}

// ---------------- aggregation: warp-per-node CSR gather over all 3 sets
__global__ void k_agg(const int* __restrict__ e0, const int* __restrict__ e1,
                      const int* __restrict__ e2) {
    int w = (blockIdx.x * blockDim.x + threadIdx.x) >> 5;
    if (w >= NN) return;
    int lane = threadIdx.x & 31;
    const float* src = (const float*)g_xw;
    float4 acc = make_float4(0, 0, 0, 0);
#pragma unroll
    for (int s = 0; s < 3; ++s) {
        int c = g_cnt[s][w];
        if (c == 0) continue;
        int o = g_off[s][w];
        float dc = g_dinv[s][w];
        const int* rows = (s == 0) ? e0 : (s == 1) ? e1 : e2;
        float4 pa = make_float4(0, 0, 0, 0);
        for (int k = 0; k < c; ++k) {
            int e = g_perm[s][o + k];
            int r = rows[e];
            float wt = g_ew[s][e] * g_dinv[s][r];
            float4 v = *(const float4*)(src + (size_t)r * FF + lane * 4);
            pa.x = fmaf(wt, v.x, pa.x);
            pa.y = fmaf(wt, v.y, pa.y);
            pa.z = fmaf(wt, v.z, pa.z);
            pa.w = fmaf(wt, v.w, pa.w);
        }
        acc.x = fmaf(dc, pa.x, acc.x);
        acc.y = fmaf(dc, pa.y, acc.y);
        acc.z = fmaf(dc, pa.z, acc.z);
        acc.w = fmaf(dc, pa.w, acc.w);
    }
    *(float4*)(g_agg + (size_t)w * FF + lane * 4) = acc;
}

// ---------------- bias + relu + BN stats (in place on g_agg)
__global__ void k_stats(const float* __restrict__ bias, int layer) {
    int c = threadIdx.x;
    float s = 0.f, q = 0.f;
    float b3 = 3.f * bias[c];
    for (int n = blockIdx.x; n < NN; n += gridDim.x) {
        float v = g_agg[(size_t)n * FF + c] + b3;
        v = fmaxf(v, 0.f);
        g_agg[(size_t)n * FF + c] = v;
        s += v;
        q += v * v;
    }
    atomicAdd(&g_bnsum[2 * layer][c], s);
    atomicAdd(&g_bnsum[2 * layer + 1][c], q);
}

__global__ void k_bnfin(int layer) {
    int c = threadIdx.x;
    float mu = g_bnsum[2 * layer][c] / (float)NN;
    float var = g_bnsum[2 * layer + 1][c] / (float)NN - mu * mu;
    g_bnp[2 * layer][c] = mu;
    g_bnp[2 * layer + 1][c] = rsqrtf(var + 1e-5f);
}

__global__ void k_bnapply(const float* __restrict__ gamma, const float* __restrict__ beta) {
    int i = blockIdx.x * blockDim.x + threadIdx.x;
    if (i >= NN * 32) return;
    int cb = (i & 31) * 4;
    float4 v = ((float4*)g_agg)[i];
    v.x = fmaxf((v.x - g_bnp[0][cb + 0]) * g_bnp[1][cb + 0] * gamma[cb + 0] + beta[cb + 0], 0.f);
    v.y = fmaxf((v.y - g_bnp[0][cb + 1]) * g_bnp[1][cb + 1] * gamma[cb + 1] + beta[cb + 1], 0.f);
    v.z = fmaxf((v.z - g_bnp[0][cb + 2]) * g_bnp[1][cb + 2] * gamma[cb + 2] + beta[cb + 2], 0.f);
    v.w = fmaxf((v.w - g_bnp[0][cb + 3]) * g_bnp[1][cb + 3] * gamma[cb + 3] + beta[cb + 3], 0.f);
    ((float4*)g_agg)[i] = v;
}

__global__ void k_final(const float* __restrict__ x, const float* __restrict__ gamma,
                        const float* __restrict__ beta, float* __restrict__ out) {
    int i = blockIdx.x * blockDim.x + threadIdx.x;
    if (i >= NN * 32) return;
    int cb = (i & 31) * 4;
    float4 v = ((const float4*)g_agg)[i];
    float4 xv = ((const float4*)x)[i];
    v.x = (v.x - g_bnp[2][cb + 0]) * g_bnp[3][cb + 0] * gamma[cb + 0] + beta[cb + 0] + xv.x;
    v.y = (v.y - g_bnp[2][cb + 1]) * g_bnp[3][cb + 1] * gamma[cb + 1] + beta[cb + 1] + xv.y;
    v.z = (v.z - g_bnp[2][cb + 2]) * g_bnp[3][cb + 2] * gamma[cb + 2] + beta[cb + 2] + xv.z;
    v.w = (v.w - g_bnp[2][cb + 3]) * g_bnp[3][cb + 3] * gamma[cb + 3] + beta[cb + 3] + xv.w;
    ((float4*)out)[i] = v;
}

// ---------------- launch ----------------
extern "C" void kernel_launch(void* const* d_in, const int* in_sizes, int n_in,
                              void* d_out, int out_size) {
    const float* x   = (const float*)d_in[0];
    const int*   e0  = (const int*)d_in[1];
    const int*   e1  = (const int*)d_in[2];
    const int*   e2  = (const int*)d_in[3];
    const float* Wa1 = (const float*)d_in[4];
    const float* ba1 = (const float*)d_in[5];
    const float* Wa2 = (const float*)d_in[6];
    const float* ba2 = (const float*)d_in[7];
    const float* W0  = (const float*)d_in[8];
    const float* b0  = (const float*)d_in[9];
    const float* W1  = (const float*)d_in[10];
    const float* b1  = (const float*)d_in[11];
    const float* g0  = (const float*)d_in[12];
    const float* be0 = (const float*)d_in[13];
    const float* g1  = (const float*)d_in[14];
    const float* be1 = (const float*)d_in[15];
    float* out = (float*)d_out;

    const int SMEM = (128 * 132 + 2 * 8 * 132) * 4;  // 76032 B for k_gemm
    cudaFuncSetAttribute(k_gemm, cudaFuncAttributeMaxDynamicSharedMemorySize, SMEM);
    cudaFuncSetAttribute(k_edge_mlp_mma, cudaFuncAttributeMaxDynamicSharedMemorySize,
                         SM_EMLP_BYTES);

    k_zero<<<(3 * NN + 255) / 256, 256>>>();
    k_count<<<(3 * EE + 255) / 256, 256>>>(e0, e1, e2);
    k_scan<<<3, 1024>>>();
    k_fill<<<(3 * EE + 255) / 256, 256>>>(e0, e1, e2);

    k_edge_mlp_mma<<<148, 256, SM_EMLP_BYTES>>>(x, e0, e1, e2, Wa1, ba1, Wa2, ba2);
    k_deg<<<(3 * NN + 255) / 256, 256>>>();

    // layer 0
    k_gemm<<<NP / 128, 256, SMEM>>>(x, NN, W0, 1);
    k_agg<<<(NN * 32 + 255) / 256, 256>>>(e0, e1, e2);
    k_stats<<<512, 128>>>(b0, 0);
    k_bnfin<<<1, 128>>>(0);
    k_bnapply<<<(NN * 32 + 255) / 256, 256>>>(g0, be0);

    // layer 1
    k_gemm<<<NP / 128, 256, SMEM>>>(nullptr, NP, W1, 0);
    k_agg<<<(NN * 32 + 255) / 256, 256>>>(e0, e1, e2);
    k_stats<<<512, 128>>>(b1, 1);
    k_bnfin<<<1, 128>>>(1);
    k_final<<<(NN * 32 + 255) / 256, 256>>>(x, g1, be1, out);
}

// round 4
// speedup vs baseline: 2.0635x; 1.4972x over previous
#include <cuda_runtime.h>
#include <cuda_fp16.h>
#include <cstdint>

#define NN 50000
#define NP 50048          // 391 * 128
#define FF 128
#define EE 800000
#define NTILES 3125       // EE / 256
#define TTILES 9375       // 3 * NTILES

// ---------------- scratch (device globals; no allocation) ----------------
__device__ float g_ew[3][EE];
__device__ int   g_perm[3][EE];
__device__ int   g_cnt[3][NN];
__device__ int   g_off[3][NN];
__device__ int   g_cur[3][NN];
__device__ float g_dinv[3][NN];
__device__ float g_xw[(size_t)NP * FF];    // xW0, then hW1
__device__ float g_agg[(size_t)NP * FF];   // agg0 -> h (in place) -> agg1
__device__ float g_bnsum[4][FF];           // sum0, sq0, sum1, sq1
__device__ float g_bnp[4][FF];             // mu0, rs0, mu1, rs1

// packed fp32x2 FMA (Blackwell)
#define FMA2(acc, a, b) asm("fma.rn.f32x2 %0, %1, %2, %0;" : "+l"(acc) : "l"(a), "l"(b))

__device__ __forceinline__ uint32_t pack_h2(float lo, float hi) {
    __half2 h = __floats2half2_rn(lo, hi);   // .x = lo (even k), .y = hi (odd k)
    return *reinterpret_cast<uint32_t*>(&h);
}

// warp-level fp16 tensor-core MMA, m16n8k16 (native HMMA on all sm_75+)
__device__ __forceinline__ void mma16(float* c, const uint32_t* a, uint32_t b0, uint32_t b1) {
    asm volatile(
        "mma.sync.aligned.m16n8k16.row.col.f32.f16.f16.f32 "
        "{%0,%1,%2,%3}, {%4,%5,%6,%7}, {%8,%9}, {%0,%1,%2,%3};"
        : "+f"(c[0]), "+f"(c[1]), "+f"(c[2]), "+f"(c[3])
        : "r"(a[0]), "r"(a[1]), "r"(a[2]), "r"(a[3]), "r"(b0), "r"(b1));
}

// ---------------- small setup kernels ----------------
__global__ void k_zero() {
    int i = blockIdx.x * blockDim.x + threadIdx.x;
    if (i < 3 * NN) (&g_cnt[0][0])[i] = 0;
    if (i < 4 * FF) (&g_bnsum[0][0])[i] = 0.f;
}

__global__ void k_count(const int* __restrict__ e0, const int* __restrict__ e1,
                        const int* __restrict__ e2) {
    int i = blockIdx.x * blockDim.x + threadIdx.x;
    if (i >= 3 * EE) return;
    int s = i / EE, j = i - s * EE;
    const int* col = (s == 0 ? e0 : s == 1 ? e1 : e2) + EE;
    atomicAdd(&g_cnt[s][col[j]], 1);
}

__global__ void k_scan() {
    __shared__ int sh[1024];
    __shared__ int carry;
    int s = blockIdx.x;
    int tid = threadIdx.x;
    if (tid == 0) carry = 0;
    __syncthreads();
    for (int base = 0; base < NN; base += 1024) {
        int i = base + tid;
        int v = (i < NN) ? g_cnt[s][i] : 0;
        sh[tid] = v;
        __syncthreads();
        for (int off = 1; off < 1024; off <<= 1) {
            int t = (tid >= off) ? sh[tid - off] : 0;
            __syncthreads();
            sh[tid] += t;
            __syncthreads();
        }
        int excl = sh[tid] - v;
        if (i < NN) {
            int o = carry + excl;
            g_off[s][i] = o;
            g_cur[s][i] = o;
        }
        int tot = sh[1023];
        __syncthreads();
        if (tid == 0) carry += tot;
        __syncthreads();
    }
}

__global__ void k_fill(const int* __restrict__ e0, const int* __restrict__ e1,
                       const int* __restrict__ e2) {
    int i = blockIdx.x * blockDim.x + threadIdx.x;
    if (i >= 3 * EE) return;
    int s = i / EE, j = i - s * EE;
    const int* col = (s == 0 ? e0 : s == 1 ? e1 : e2) + EE;
    int pos = atomicAdd(&g_cur[s][col[j]], 1);
    g_perm[s][pos] = j;
}

__global__ void k_deg() {
    int i = blockIdx.x * blockDim.x + threadIdx.x;
    if (i >= 3 * NN) return;
    int s = i / NN, n = i - s * NN;
    int o = g_off[s][n], c = g_cnt[s][n];
    float d = 0.f;
    for (int k = 0; k < c; ++k) d += g_ew[s][g_perm[s][o + k]];
    g_dinv[s][n] = (c > 0) ? rsqrtf(d) : 0.f;
}

// ---------------- edge MLP via fp16 mma.sync tensor cores ----------------
// persistent: 148 CTAs x 256 threads; tile = 256 edges x 128 H, K=128.
// A/W in SMEM as u32(fp16x2), row stride 68 u32 -> conflict-free fragment reads.
#define AS_U32 68
#define SM_WOFF   (256 * AS_U32)                // u32 offset of W
#define SM_B1OFF  (SM_WOFF + 128 * AS_U32)
#define SM_W2OFF  (SM_B1OFF + 128)
#define SM_EMLP_BYTES ((SM_W2OFF + 128) * 4)    // 105472 B

__global__ void __launch_bounds__(256, 1) k_edge_mlp_mma(
    const float* __restrict__ x,
    const int* __restrict__ e0, const int* __restrict__ e1, const int* __restrict__ e2,
    const float* __restrict__ Wa1, const float* __restrict__ ba1,
    const float* __restrict__ Wa2, const float* __restrict__ ba2) {
    extern __shared__ uint32_t As[];
    uint32_t* Ws = As + SM_WOFF;
    float* Bb = (float*)(As + SM_B1OFF);
    float* W2 = (float*)(As + SM_W2OFF);

    const int tid = threadIdx.x;
    const int w = tid >> 5;
    const int l = tid & 31;
    const int g = l >> 2;
    const int t = l & 3;
    const int rowbase = w * 32;

    int cur_set = -1;
    const int* ei = e0;
    float b2 = 0.f;

    for (int T = blockIdx.x; T < TTILES; T += 148) {
        int set = T / NTILES;
        int tile = T - set * NTILES;
        if (set != cur_set) {
            __syncthreads();   // previous tile's Ws reads complete
            const float* W = Wa1 + set * 128 * 128;
#pragma unroll
            for (int it = 0; it < 16; ++it) {
                int idx = tid + it * 256;
                int h = idx >> 5, f = (idx & 31) * 4;
                float4 v = *(const float4*)(W + h * 128 + f);
                uint32_t* dst = Ws + h * AS_U32 + f / 2;
                dst[0] = pack_h2(v.x, v.y);
                dst[1] = pack_h2(v.z, v.w);
            }
            if (tid < 128) {
                Bb[tid] = ba1[set * 128 + tid];
                W2[tid] = Wa2[set * 128 + tid];
            }
            ei = (set == 0) ? e0 : (set == 1) ? e1 : e2;
            b2 = ba2[set];
            cur_set = set;
            __syncthreads();
        }
        const int eb = tile * 256;

        // ---- stage A = fp16(|x[r] - x[c]|), 64 u32 per row, stride 68
        {
            int r = ei[eb + tid];
            int c = ei[EE + eb + tid];
            const float4* xr = (const float4*)(x + (size_t)r * FF);
            const float4* xc = (const float4*)(x + (size_t)c * FF);
            uint32_t* arow = As + tid * AS_U32;
#pragma unroll
            for (int j = 0; j < 32; ++j) {
                float4 a = xr[j], b = xc[j];
                uint2 o;
                o.x = pack_h2(fabsf(a.x - b.x), fabsf(a.y - b.y));
                o.y = pack_h2(fabsf(a.z - b.z), fabsf(a.w - b.w));
                *(uint2*)(arow + 2 * j) = o;
            }
        }
        __syncthreads();

        // ---- MMA mainloop: warp computes rows [rowbase, rowbase+32) x 128 H
        float acc[2][16][4];
#pragma unroll
        for (int mb = 0; mb < 2; ++mb)
#pragma unroll
            for (int nb = 0; nb < 16; ++nb)
#pragma unroll
                for (int q = 0; q < 4; ++q) acc[mb][nb][q] = 0.f;

#pragma unroll
        for (int kb = 0; kb < 8; ++kb) {
            const int kc = kb * 8 + t;
            uint32_t af[2][4];
#pragma unroll
            for (int mb = 0; mb < 2; ++mb) {
                int m0 = rowbase + mb * 16 + g;
                af[mb][0] = As[m0 * AS_U32 + kc];
                af[mb][1] = As[(m0 + 8) * AS_U32 + kc];
                af[mb][2] = As[m0 * AS_U32 + kc + 4];
                af[mb][3] = As[(m0 + 8) * AS_U32 + kc + 4];
            }
#pragma unroll
            for (int nb = 0; nb < 16; ++nb) {
                uint32_t b0 = Ws[(nb * 8 + g) * AS_U32 + kc];
                uint32_t b1 = Ws[(nb * 8 + g) * AS_U32 + kc + 4];
                mma16(acc[0][nb], af[0], b0, b1);
                mma16(acc[1][nb], af[1], b0, b1);
            }
        }

        // ---- epilogue: relu(acc + ba1) . Wa2, reduce over H, sigmoid
        float s[4] = {0.f, 0.f, 0.f, 0.f};
#pragma unroll
        for (int nb = 0; nb < 16; ++nb) {
            int h0 = nb * 8 + 2 * t;
            float bb0 = Bb[h0], bb1 = Bb[h0 + 1];
            float w20 = W2[h0], w21 = W2[h0 + 1];
            s[0] += fmaxf(acc[0][nb][0] + bb0, 0.f) * w20 + fmaxf(acc[0][nb][1] + bb1, 0.f) * w21;
            s[1] += fmaxf(acc[0][nb][2] + bb0, 0.f) * w20 + fmaxf(acc[0][nb][3] + bb1, 0.f) * w21;
            s[2] += fmaxf(acc[1][nb][0] + bb0, 0.f) * w20 + fmaxf(acc[1][nb][1] + bb1, 0.f) * w21;
            s[3] += fmaxf(acc[1][nb][2] + bb0, 0.f) * w20 + fmaxf(acc[1][nb][3] + bb1, 0.f) * w21;
        }
#pragma unroll
        for (int i = 0; i < 4; ++i) {
            float v = s[i];
            v += __shfl_xor_sync(0xffffffffu, v, 1);
            v += __shfl_xor_sync(0xffffffffu, v, 2);
            if (t == 0) {
                int rl = rowbase + (i >> 1) * 16 + (i & 1) * 8 + g;
                float z = v + b2;
                g_ew[set][eb + rl] = 1.f / (1.f + expf(-z));
            }
        }
        __syncthreads();   // A reuse safe for next tile
    }
}

// ---------------- node GEMM: C[n][h] = sum_f A[n][f] * W[h][f], C = g_xw
__global__ void __launch_bounds__(256) k_gemm(
    const float* __restrict__ Aext, int nrows, const float* __restrict__ W, int useExt) {
    extern __shared__ float smf[];
    float* Ws = smf;
    float* As2 = smf + 128 * 132;
    const float* A = useExt ? Aext : (const float*)g_agg;
    const int tid = threadIdx.x;
#pragma unroll
    for (int it = 0; it < 16; ++it) {
        int idx = tid + 256 * it;
        int h = idx >> 5, f4 = idx & 31;
        float4 w = *(const float4*)(W + h * 128 + f4 * 4);
        Ws[(f4 * 4 + 0) * 132 + h] = w.x;
        Ws[(f4 * 4 + 1) * 132 + h] = w.y;
        Ws[(f4 * 4 + 2) * 132 + h] = w.z;
        Ws[(f4 * 4 + 3) * 132 + h] = w.w;
    }
    const int n0 = blockIdx.x * 128;
    const int eL = tid >> 1;
    const int jL = (tid & 1) * 4;
    const int nr = n0 + eL;
    const bool ok = nr < nrows;
    const float* ap = A + (size_t)nr * FF;
    const int tx = tid & 15, ty = tid >> 4;
    {
        float4 a = ok ? *(const float4*)(ap + jL) : make_float4(0, 0, 0, 0);
        As2[(jL + 0) * 132 + eL] = a.x;
        As2[(jL + 1) * 132 + eL] = a.y;
        As2[(jL + 2) * 132 + eL] = a.z;
        As2[(jL + 3) * 132 + eL] = a.w;
    }
    __syncthreads();

    unsigned long long acc[8][4];
#pragma unroll
    for (int r = 0; r < 8; ++r)
#pragma unroll
        for (int q = 0; q < 4; ++q) acc[r][q] = 0ull;

    for (int kt = 0; kt < 16; ++kt) {
        int buf = kt & 1;
        if (kt < 15) {
            int k0 = (kt + 1) * 8;
            float4 a = ok ? *(const float4*)(ap + k0 + jL) : make_float4(0, 0, 0, 0);
            float* D = As2 + (buf ^ 1) * 8 * 132;
            D[(jL + 0) * 132 + eL] = a.x;
            D[(jL + 1) * 132 + eL] = a.y;
            D[(jL + 2) * 132 + eL] = a.z;
            D[(jL + 3) * 132 + eL] = a.w;
        }
        const float* Ab = As2 + buf * 8 * 132;
#pragma unroll
        for (int kk = 0; kk < 8; ++kk) {
            const float* wrow = Ws + (kt * 8 + kk) * 132 + tx * 8;
            ulonglong2 b0 = *(const ulonglong2*)(wrow);
            ulonglong2 b1 = *(const ulonglong2*)(wrow + 4);
            float4 a0 = *(const float4*)(Ab + kk * 132 + ty * 8);
            float4 a1 = *(const float4*)(Ab + kk * 132 + ty * 8 + 4);
            float av[8] = {a0.x, a0.y, a0.z, a0.w, a1.x, a1.y, a1.z, a1.w};
#pragma unroll
            for (int r = 0; r < 8; ++r) {
                unsigned long long ad;
                unsigned au = __float_as_uint(av[r]);
                asm("mov.b64 %0, {%1,%1};" : "=l"(ad) : "r"(au));
                FMA2(acc[r][0], ad, b0.x);
                FMA2(acc[r][1], ad, b0.y);
                FMA2(acc[r][2], ad, b1.x);
                FMA2(acc[r][3], ad, b1.y);
            }
        }
        __syncthreads();
    }
#pragma unroll
    for (int r = 0; r < 8; ++r) {
        int n = n0 + ty * 8 + r;
        float4 o0, o1;
        o0.x = __uint_as_float((unsigned)acc[r][0]);
        o0.y = __uint_as_float((unsigned)(acc[r][0] >> 32));
        o0.z = __uint_as_float((unsigned)acc[r][1]);
        o0.w = __uint_as_float((unsigned)(acc[r][1] >> 32));
        o1.x = __uint_as_float((unsigned)acc[r][2]);
        o1.y = __uint_as_float((unsigned)(acc[r][2] >> 32));
        o1.z = __uint_as_float((unsigned)acc[r][3]);
        o1.w = __uint_as_float((unsigned)(acc[r][3] >> 32));
        *(float4*)(g_xw + (size_t)n * FF + tx * 8) = o0;
        *(float4*)(g_xw + (size_t)n * FF + tx * 8 + 4) = o1;
    }
}

// ---------------- aggregation: warp-per-node CSR gather over all 3 sets
__global__ void k_agg(const int* __restrict__ e0, const int* __restrict__ e1,
                      const int* __restrict__ e2) {
    int w = (blockIdx.x * blockDim.x + threadIdx.x) >> 5;
    if (w >= NN) return;
    int lane = threadIdx.x & 31;
    const float* src = (const float*)g_xw;
    float4 acc = make_float4(0, 0, 0, 0);
#pragma unroll
    for (int s = 0; s < 3; ++s) {
        int c = g_cnt[s][w];
        if (c == 0) continue;
        int o = g_off[s][w];
        float dc = g_dinv[s][w];
        const int* rows = (s == 0) ? e0 : (s == 1) ? e1 : e2;
        float4 pa = make_float4(0, 0, 0, 0);
        for (int k = 0; k < c; ++k) {
            int e = g_perm[s][o + k];
            int r = rows[e];
            float wt = g_ew[s][e] * g_dinv[s][r];
            float4 v = *(const float4*)(src + (size_t)r * FF + lane * 4);
            pa.x = fmaf(wt, v.x, pa.x);
            pa.y = fmaf(wt, v.y, pa.y);
            pa.z = fmaf(wt, v.z, pa.z);
            pa.w = fmaf(wt, v.w, pa.w);
        }
        acc.x = fmaf(dc, pa.x, acc.x);
        acc.y = fmaf(dc, pa.y, acc.y);
        acc.z = fmaf(dc, pa.z, acc.z);
        acc.w = fmaf(dc, pa.w, acc.w);
    }
    *(float4*)(g_agg + (size_t)w * FF + lane * 4) = acc;
}

// ---------------- bias + relu + BN stats (in place on g_agg)
__global__ void k_stats(const float* __restrict__ bias, int layer) {
    int c = threadIdx.x;
    float s = 0.f, q = 0.f;
    float b3 = 3.f * bias[c];
    for (int n = blockIdx.x; n < NN; n += gridDim.x) {
        float v = g_agg[(size_t)n * FF + c] + b3;
        v = fmaxf(v, 0.f);
        g_agg[(size_t)n * FF + c] = v;
        s += v;
        q += v * v;
    }
    atomicAdd(&g_bnsum[2 * layer][c], s);
    atomicAdd(&g_bnsum[2 * layer + 1][c], q);
}

__global__ void k_bnfin(int layer) {
    int c = threadIdx.x;
    float mu = g_bnsum[2 * layer][c] / (float)NN;
    float var = g_bnsum[2 * layer + 1][c] / (float)NN - mu * mu;
    g_bnp[2 * layer][c] = mu;
    g_bnp[2 * layer + 1][c] = rsqrtf(var + 1e-5f);
}

__global__ void k_bnapply(const float* __restrict__ gamma, const float* __restrict__ beta) {
    int i = blockIdx.x * blockDim.x + threadIdx.x;
    if (i >= NN * 32) return;
    int cb = (i & 31) * 4;
    float4 v = ((float4*)g_agg)[i];
    v.x = fmaxf((v.x - g_bnp[0][cb + 0]) * g_bnp[1][cb + 0] * gamma[cb + 0] + beta[cb + 0], 0.f);
    v.y = fmaxf((v.y - g_bnp[0][cb + 1]) * g_bnp[1][cb + 1] * gamma[cb + 1] + beta[cb + 1], 0.f);
    v.z = fmaxf((v.z - g_bnp[0][cb + 2]) * g_bnp[1][cb + 2] * gamma[cb + 2] + beta[cb + 2], 0.f);
    v.w = fmaxf((v.w - g_bnp[0][cb + 3]) * g_bnp[1][cb + 3] * gamma[cb + 3] + beta[cb + 3], 0.f);
    ((float4*)g_agg)[i] = v;
}

__global__ void k_final(const float* __restrict__ x, const float* __restrict__ gamma,
                        const float* __restrict__ beta, float* __restrict__ out) {
    int i = blockIdx.x * blockDim.x + threadIdx.x;
    if (i >= NN * 32) return;
    int cb = (i & 31) * 4;
    float4 v = ((const float4*)g_agg)[i];
    float4 xv = ((const float4*)x)[i];
    v.x = (v.x - g_bnp[2][cb + 0]) * g_bnp[3][cb + 0] * gamma[cb + 0] + beta[cb + 0] + xv.x;
    v.y = (v.y - g_bnp[2][cb + 1]) * g_bnp[3][cb + 1] * gamma[cb + 1] + beta[cb + 1] + xv.y;
    v.z = (v.z - g_bnp[2][cb + 2]) * g_bnp[3][cb + 2] * gamma[cb + 2] + beta[cb + 2] + xv.z;
    v.w = (v.w - g_bnp[2][cb + 3]) * g_bnp[3][cb + 3] * gamma[cb + 3] + beta[cb + 3] + xv.w;
    ((float4*)out)[i] = v;
}

// ---------------- launch ----------------
extern "C" void kernel_launch(void* const* d_in, const int* in_sizes, int n_in,
                              void* d_out, int out_size) {
    const float* x   = (const float*)d_in[0];
    const int*   e0  = (const int*)d_in[1];
    const int*   e1  = (const int*)d_in[2];
    const int*   e2  = (const int*)d_in[3];
    const float* Wa1 = (const float*)d_in[4];
    const float* ba1 = (const float*)d_in[5];
    const float* Wa2 = (const float*)d_in[6];
    const float* ba2 = (const float*)d_in[7];
    const float* W0  = (const float*)d_in[8];
    const float* b0  = (const float*)d_in[9];
    const float* W1  = (const float*)d_in[10];
    const float* b1  = (const float*)d_in[11];
    const float* g0  = (const float*)d_in[12];
    const float* be0 = (const float*)d_in[13];
    const float* g1  = (const float*)d_in[14];
    const float* be1 = (const float*)d_in[15];
    float* out = (float*)d_out;

    const int SMEM = (128 * 132 + 2 * 8 * 132) * 4;  // 76032 B for k_gemm
    cudaFuncSetAttribute(k_gemm, cudaFuncAttributeMaxDynamicSharedMemorySize, SMEM);
    cudaFuncSetAttribute(k_edge_mlp_mma, cudaFuncAttributeMaxDynamicSharedMemorySize,
                         SM_EMLP_BYTES);

    // order chosen so the edge-MLP kernel is the 4th launch (ncu capture slot)
    k_zero<<<(3 * NN + 255) / 256, 256>>>();
    k_count<<<(3 * EE + 255) / 256, 256>>>(e0, e1, e2);
    k_scan<<<3, 1024>>>();
    k_edge_mlp_mma<<<148, 256, SM_EMLP_BYTES>>>(x, e0, e1, e2, Wa1, ba1, Wa2, ba2);
    k_fill<<<(3 * EE + 255) / 256, 256>>>(e0, e1, e2);
    k_deg<<<(3 * NN + 255) / 256, 256>>>();

    // layer 0
    k_gemm<<<NP / 128, 256, SMEM>>>(x, NN, W0, 1);
    k_agg<<<(NN * 32 + 255) / 256, 256>>>(e0, e1, e2);
    k_stats<<<512, 128>>>(b0, 0);
    k_bnfin<<<1, 128>>>(0);
    k_bnapply<<<(NN * 32 + 255) / 256, 256>>>(g0, be0);

    // layer 1
    k_gemm<<<NP / 128, 256, SMEM>>>(nullptr, NP, W1, 0);
    k_agg<<<(NN * 32 + 255) / 256, 256>>>(e0, e1, e2);
    k_stats<<<512, 128>>>(b1, 1);
    k_bnfin<<<1, 128>>>(1);
    k_final<<<(NN * 32 + 255) / 256, 256>>>(x, g1, be1, out);
}